// round 5
// baseline (speedup 1.0000x reference)
#include <cuda_runtime.h>
#include <cstdint>

// ---------------------------------------------------------------------------
// Problem constants
// ---------------------------------------------------------------------------
#define M_TOTAL 16384
#define N_W     1024
#define K_TOTAL 1024

// GEMM tiling: CTA 128x128, 8 warps of 64x32, BK=32
#define BM 128
#define BN 128
#define BK 32
#define NITER (K_TOTAL / BK)   // 32

#define TROW 40                 // 32 + 8 pad: conflict-free LDS.64 frag loads
#define TILE_F (128 * TROW)     // 5120 floats (A and B tiles identical shape)
#define SMEM_BYTES (4 * TILE_F * 4)   // 2 stages x (A+B) = 81920 B

// Scratch
__device__ float g_qkv[3ull * M_TOTAL * N_W];     // QKV projections
__device__ float g_xr[(size_t)M_TOTAL * K_TOTAL]; // x: tf32, k-interleaved
__device__ float g_wt[3ull * K_TOTAL * N_W];      // W: tf32, [w][nb][kc][n][32] tiles

// ---------------------------------------------------------------------------
// Helpers
// ---------------------------------------------------------------------------
__device__ __forceinline__ uint32_t smem_u32(const void* p) {
    uint32_t a;
    asm("{ .reg .u64 t; cvta.to.shared.u64 t, %1; cvt.u32.u64 %0, t; }" : "=r"(a) : "l"(p));
    return a;
}

#define CP_ASYNC_16(dst_u32, src_ptr) \
    asm volatile("cp.async.cg.shared.global [%0], [%1], 16;" \
                 :: "r"(dst_u32), "l"(src_ptr) : "memory")
#define CP_COMMIT() asm volatile("cp.async.commit_group;" ::: "memory")
#define CP_WAIT(n)  asm volatile("cp.async.wait_group %0;" :: "n"(n) : "memory")

__device__ __forceinline__ float tf32r(float f) {
    uint32_t u;
    asm("cvt.rna.tf32.f32 %0, %1;" : "=r"(u) : "f"(f));
    return __uint_as_float(u);
}

__device__ __forceinline__ void mma_tf32(float* d, const uint32_t* a, const uint32_t* b) {
    asm volatile(
        "mma.sync.aligned.m16n8k8.row.col.f32.tf32.tf32.f32 "
        "{%0,%1,%2,%3}, {%4,%5,%6,%7}, {%8,%9}, {%0,%1,%2,%3};"
        : "+f"(d[0]), "+f"(d[1]), "+f"(d[2]), "+f"(d[3])
        : "r"(a[0]), "r"(a[1]), "r"(a[2]), "r"(a[3]),
          "r"(b[0]), "r"(b[1]));
}

// ---------------------------------------------------------------------------
// round_x: tf32-round + per-8-group k-interleave pos(k)=2*(k&3)+(k>>2)
// ---------------------------------------------------------------------------
__global__ void __launch_bounds__(256)
round_x_kernel(const float* __restrict__ x)
{
    size_t g = (size_t)blockIdx.x * 256 + threadIdx.x;   // 8-float group id
    const float4 a = *(const float4*)(x + g * 8);
    const float4 b = *(const float4*)(x + g * 8 + 4);
    float4 o0, o1;
    o0.x = tf32r(a.x); o0.y = tf32r(b.x); o0.z = tf32r(a.y); o0.w = tf32r(b.y);
    o1.x = tf32r(a.z); o1.y = tf32r(b.z); o1.z = tf32r(a.w); o1.w = tf32r(b.w);
    *(float4*)(g_xr + g * 8)     = o0;
    *(float4*)(g_xr + g * 8 + 4) = o1;
}

// ---------------------------------------------------------------------------
// round_w: tf32-round + transpose W[k][n] into n-major, k-interleaved tiles.
// ---------------------------------------------------------------------------
__global__ void __launch_bounds__(256)
round_w_kernel(const float* __restrict__ Wq, const float* __restrict__ Wk,
               const float* __restrict__ Wv)
{
    __shared__ float s[32][136];
    const int kc = blockIdx.x, nb = blockIdx.y, w = blockIdx.z;
    const int tid = threadIdx.x;
    const float* W = (w == 0) ? Wq : (w == 1 ? Wk : Wv);

    #pragma unroll
    for (int i = 0; i < 4; i++) {
        int idx = tid + i * 256;
        int kr = idx >> 5, nc = idx & 31;
        float4 v = *(const float4*)(W + (size_t)(kc * 32 + kr) * N_W + nb * 128 + nc * 4);
        v.x = tf32r(v.x); v.y = tf32r(v.y); v.z = tf32r(v.z); v.w = tf32r(v.w);
        *(float4*)(&s[kr][nc * 4]) = v;
    }
    __syncthreads();

    float* out = g_wt + ((((size_t)w * 8 + nb) * 32 + kc) * 4096);
    #pragma unroll
    for (int i = 0; i < 4; i++) {
        int fidx = tid + i * 256;
        int n = fidx >> 3, pq = fidx & 7;
        float4 o;
        #pragma unroll
        for (int e = 0; e < 4; e++) {
            int p = pq * 4 + e;
            int k = (p & ~7) + (((p & 7) >> 1) + 4 * (p & 1));
            ((float*)&o)[e] = s[k][n];
        }
        *(float4*)(out + n * 32 + pq * 4) = o;
    }
}

// ---------------------------------------------------------------------------
// Fused QKV GEMM: 256 threads, 8 warps (2m x 4n) of 64x32 each, occ 2.
// 4 warps/SMSP for latency hiding (was 2).
// ---------------------------------------------------------------------------
__global__ void __launch_bounds__(256, 2)
qkv_gemm_kernel(const float* __restrict__ bq, const float* __restrict__ bk,
                const float* __restrict__ bv)
{
    extern __shared__ float smem[];
    float* As = smem;                       // [2][128][TROW]
    float* Bs = smem + 2 * TILE_F;          // [2][128][TROW]
    const uint32_t sA = smem_u32(As);
    const uint32_t sB = smem_u32(Bs);

    const int tid = threadIdx.x;
    const int wid = tid >> 5;
    const int lane = tid & 31;
    const int r = lane >> 2;
    const int c = lane & 3;

    const int ntile = blockIdx.x;           // 0..23
    const int mtile = blockIdx.y;           // 0..127
    const int wsel  = ntile >> 3;
    const int nb    = ntile & 7;
    const int n0    = nb * BN;
    const int m0    = mtile * BM;
    const float* Wt   = g_wt + (((size_t)wsel * 8 + nb) * 32) * 4096;
    const float* bias = (wsel == 0) ? bq : (wsel == 1 ? bk : bv);

    const int wm = wid & 1;                 // 64-row group
    const int wn = wid >> 1;                // 32-col group (0..3)

    auto load_tiles = [&](int kc, int buf) {
        const float* Ag = g_xr + (size_t)m0 * K_TOTAL + (size_t)kc * BK;
        const float* Bg = Wt + (size_t)kc * 4096;
        #pragma unroll
        for (int i = 0; i < 4; i++) {
            int idx = tid + i * 256;         // 0..1023
            int row = idx >> 3, q = idx & 7;
            uint32_t adst = sA + (uint32_t)(((buf * BM + row) * TROW + q * 4) * 4);
            CP_ASYNC_16(adst, Ag + (size_t)row * K_TOTAL + q * 4);
            uint32_t bdst = sB + (uint32_t)(((buf * BN + row) * TROW + q * 4) * 4);
            CP_ASYNC_16(bdst, Bg + row * 32 + q * 4);
        }
        CP_COMMIT();
    };

    float acc[4][4][4];
    #pragma unroll
    for (int mt = 0; mt < 4; mt++)
        #pragma unroll
        for (int nt = 0; nt < 4; nt++)
            #pragma unroll
            for (int i = 0; i < 4; i++) acc[mt][nt][i] = 0.f;

    load_tiles(0, 0);

    for (int kc = 0; kc < NITER; kc++) {
        const int buf = kc & 1;
        if (kc + 1 < NITER) {
            load_tiles(kc + 1, buf ^ 1);
            CP_WAIT(1);
        } else {
            CP_WAIT(0);
        }
        __syncthreads();

        const float* A_s = As + buf * TILE_F + (wm * 64 + r) * TROW;
        const float* B_s = Bs + buf * TILE_F + (wn * 32 + r) * TROW;

        #pragma unroll
        for (int ks = 0; ks < 4; ks++) {
            const int ko = ks * 8 + 2 * c;   // interleaved: (k, k+4) adjacent
            uint32_t af[4][4];
            #pragma unroll
            for (int mt = 0; mt < 4; mt++) {
                float2 p0 = *(const float2*)(A_s + (mt * 16) * TROW + ko);
                float2 p1 = *(const float2*)(A_s + (mt * 16 + 8) * TROW + ko);
                af[mt][0] = __float_as_uint(p0.x);
                af[mt][1] = __float_as_uint(p1.x);
                af[mt][2] = __float_as_uint(p0.y);
                af[mt][3] = __float_as_uint(p1.y);
            }
            uint32_t bf[4][2];
            #pragma unroll
            for (int nt = 0; nt < 4; nt++) {
                float2 pb = *(const float2*)(B_s + (nt * 8) * TROW + ko);
                bf[nt][0] = __float_as_uint(pb.x);
                bf[nt][1] = __float_as_uint(pb.y);
            }
            #pragma unroll
            for (int mt = 0; mt < 4; mt++)
                #pragma unroll
                for (int nt = 0; nt < 4; nt++)
                    mma_tf32(acc[mt][nt], af[mt], bf[nt]);
        }
        __syncthreads();
    }

    float* dst_w = g_qkv + (size_t)wsel * M_TOTAL * N_W;
    #pragma unroll
    for (int mt = 0; mt < 4; mt++) {
        const int row0 = m0 + wm * 64 + mt * 16 + r;
        #pragma unroll
        for (int nt = 0; nt < 4; nt++) {
            const int col = n0 + wn * 32 + nt * 8 + c * 2;
            const float b0 = __ldg(bias + col);
            const float b1 = __ldg(bias + col + 1);
            float2 v0 = make_float2(acc[mt][nt][0] + b0, acc[mt][nt][1] + b1);
            float2 v1 = make_float2(acc[mt][nt][2] + b0, acc[mt][nt][3] + b1);
            *(float2*)(dst_w + (size_t)row0 * N_W + col)       = v0;
            *(float2*)(dst_w + (size_t)(row0 + 8) * N_W + col) = v1;
        }
    }
}

// ---------------------------------------------------------------------------
// Head-attention: 4 tokens/block (56.6 KB smem -> 4 blocks/SM), 128 threads,
// 32 workers per token (1 warp per token).
// Scores: worker (ib,jb) does rows ib*4..+4, cols jb*2..+2.
// Ctx: worker does rows (sub>>4)*8..+8, cols (sub&15)*4..+4. acc = 32 regs.
// ---------------------------------------------------------------------------
#define TPB_T 4
#define RS    68
#define TSTR  (16 * RS + 4)                  // 1092
#define PSTR  16
#define PTOK  (16 * PSTR + 4)                // 260
#define ATTN_SMEM_F (3 * TPB_T * TSTR + TPB_T * PTOK)   // 14144 floats
#define ATTN_SMEM_B (ATTN_SMEM_F * 4)                   // 56576 bytes

__global__ void __launch_bounds__(128, 4)
attn_kernel(float* __restrict__ out)
{
    extern __shared__ float sm[];
    float* sq  = sm;
    float* sk  = sm + TPB_T * TSTR;
    float* sv  = sm + 2 * TPB_T * TSTR;
    float* spT = sm + 3 * TPB_T * TSTR;

    const int tid = threadIdx.x;
    const int t0 = blockIdx.x * TPB_T;

    // Stage q,k,v: 1024 float4 per tensor, coalesced.
    {
        const float* qg = g_qkv + (size_t)t0 * N_W;
        const float* kg = g_qkv + (size_t)M_TOTAL * N_W + (size_t)t0 * N_W;
        const float* vg = g_qkv + 2ull * M_TOTAL * N_W + (size_t)t0 * N_W;
        #pragma unroll
        for (int i = 0; i < 8; i++) {
            int idx = tid + i * 128;            // 0..1023
            int tok = idx >> 8, rem = idx & 255;
            int row = rem >> 4, dq = rem & 15;
            int sa = tok * TSTR + row * RS + dq * 4;
            size_t ga = (size_t)idx * 4;
            *(float4*)(sq + sa) = *(const float4*)(qg + ga);
            *(float4*)(sk + sa) = *(const float4*)(kg + ga);
            *(float4*)(sv + sa) = *(const float4*)(vg + ga);
        }
    }
    __syncthreads();

    const int tt  = tid >> 5;    // token within block (warp == token)
    const int sub = tid & 31;
    const int ib  = sub >> 3;    // 0..3 -> 4 query rows
    const int jb  = sub & 7;     // 0..7 -> 2 key cols

    // ---- scores: 4x2 block ----
    float s[4][2];
    #pragma unroll
    for (int i = 0; i < 4; i++) { s[i][0] = 0.f; s[i][1] = 0.f; }
    {
        const float* qp = sq + tt * TSTR + (ib * 4) * RS;
        const float* kp = sk + tt * TSTR + (jb * 2) * RS;
        #pragma unroll
        for (int dq = 0; dq < 16; dq++) {
            float4 qa[4], ka[2];
            #pragma unroll
            for (int i = 0; i < 4; i++) qa[i] = *(const float4*)(qp + i * RS + dq * 4);
            #pragma unroll
            for (int j = 0; j < 2; j++) ka[j] = *(const float4*)(kp + j * RS + dq * 4);
            #pragma unroll
            for (int i = 0; i < 4; i++)
                #pragma unroll
                for (int j = 0; j < 2; j++) {
                    s[i][j] = fmaf(qa[i].x, ka[j].x, s[i][j]);
                    s[i][j] = fmaf(qa[i].y, ka[j].y, s[i][j]);
                    s[i][j] = fmaf(qa[i].z, ka[j].z, s[i][j]);
                    s[i][j] = fmaf(qa[i].w, ka[j].w, s[i][j]);
                }
        }
    }

    // ---- softmax over j: reduce across 8 jb-lanes (contiguous within warp) ----
    float p[4][2];
    #pragma unroll
    for (int i = 0; i < 4; i++) {
        float s0 = s[i][0] * 0.125f, s1 = s[i][1] * 0.125f;
        float m = fmaxf(s0, s1);
        m = fmaxf(m, __shfl_xor_sync(0xffffffffu, m, 1));
        m = fmaxf(m, __shfl_xor_sync(0xffffffffu, m, 2));
        m = fmaxf(m, __shfl_xor_sync(0xffffffffu, m, 4));
        float e0 = __expf(s0 - m), e1 = __expf(s1 - m);
        float sum = e0 + e1;
        sum += __shfl_xor_sync(0xffffffffu, sum, 1);
        sum += __shfl_xor_sync(0xffffffffu, sum, 2);
        sum += __shfl_xor_sync(0xffffffffu, sum, 4);
        float inv = __frcp_rn(sum);
        p[i][0] = e0 * inv; p[i][1] = e1 * inv;
    }
    // store transposed: spT[tok][j][i]
    {
        float* pt = spT + tt * PTOK;
        #pragma unroll
        for (int j = 0; j < 2; j++) {
            float4 v = make_float4(p[0][j], p[1][j], p[2][j], p[3][j]);
            *(float4*)(pt + (jb * 2 + j) * PSTR + ib * 4) = v;
        }
    }
    __syncwarp();

    // ---- ctx: rows i0..i0+8, cols c0..c0+4 ----
    {
        const int i0 = (sub >> 4) * 8;       // 0 or 8
        const int c0 = (sub & 15) * 4;       // 0..60
        const float* pt = spT + tt * PTOK;
        const float* vp = sv + tt * TSTR + c0;
        float4 acc[8];
        #pragma unroll
        for (int i = 0; i < 8; i++) acc[i] = make_float4(0.f, 0.f, 0.f, 0.f);
        #pragma unroll
        for (int j = 0; j < 16; j++) {
            float4 vj = *(const float4*)(vp + j * RS);
            const float* pr = pt + j * PSTR + i0;
            float4 p0 = *(const float4*)(pr);
            float4 p1 = *(const float4*)(pr + 4);
            const float pj[8] = {p0.x, p0.y, p0.z, p0.w, p1.x, p1.y, p1.z, p1.w};
            #pragma unroll
            for (int i = 0; i < 8; i++) {
                acc[i].x = fmaf(pj[i], vj.x, acc[i].x);
                acc[i].y = fmaf(pj[i], vj.y, acc[i].y);
                acc[i].z = fmaf(pj[i], vj.z, acc[i].z);
                acc[i].w = fmaf(pj[i], vj.w, acc[i].w);
            }
        }
        float* ob = out + (size_t)(t0 + tt) * N_W + (size_t)i0 * 64 + c0;
        #pragma unroll
        for (int i = 0; i < 8; i++)
            *(float4*)(ob + i * 64) = acc[i];
    }
}

// ---------------------------------------------------------------------------
// Launch
// ---------------------------------------------------------------------------
extern "C" void kernel_launch(void* const* d_in, const int* in_sizes, int n_in,
                              void* d_out, int out_size)
{
    const float* x  = (const float*)d_in[0];
    const float* Wq = (const float*)d_in[1];
    const float* bq = (const float*)d_in[2];
    const float* Wk = (const float*)d_in[3];
    const float* bk = (const float*)d_in[4];
    const float* Wv = (const float*)d_in[5];
    const float* bv = (const float*)d_in[6];
    float* out = (float*)d_out;

    cudaFuncSetAttribute(qkv_gemm_kernel,
                         cudaFuncAttributeMaxDynamicSharedMemorySize, SMEM_BYTES);
    cudaFuncSetAttribute(attn_kernel,
                         cudaFuncAttributeMaxDynamicSharedMemorySize, ATTN_SMEM_B);

    round_x_kernel<<<(M_TOTAL * K_TOTAL / 8) / 256, 256>>>(x);
    {
        dim3 gw(32, 8, 3);
        round_w_kernel<<<gw, 256>>>(Wq, Wk, Wv);
    }
    dim3 grid(24, 128);
    qkv_gemm_kernel<<<grid, 256, SMEM_BYTES>>>(bq, bk, bv);
    attn_kernel<<<M_TOTAL / TPB_T, 128, ATTN_SMEM_B>>>(out);
}

// round 6
// speedup vs baseline: 1.0570x; 1.0570x over previous
#include <cuda_runtime.h>
#include <cstdint>

// ---------------------------------------------------------------------------
// Problem constants
// ---------------------------------------------------------------------------
#define M_TOTAL 16384
#define N_W     1024
#define K_TOTAL 1024

// GEMM tiling: CTA 128x128, 4 warps of 64x64, BK=32
#define BM 128
#define BN 128
#define BK 32
#define NITER (K_TOTAL / BK)   // 32

#define TROW 36                 // 32 + 4 pad: each ldsm phase hits 32 distinct banks
#define TILE_F (128 * TROW)     // 4608 floats
#define SMEM_BYTES (4 * TILE_F * 4)   // 2 stages x (A+B) = 73728 B

// Scratch
__device__ float g_qkv[3ull * M_TOTAL * N_W];     // QKV projections
__device__ float g_xr[(size_t)M_TOTAL * K_TOTAL]; // x: tf32-rounded (plain order)
__device__ float g_wt[3ull * K_TOTAL * N_W];      // W: tf32, [w][nb][kc][n][32] tiles

// ---------------------------------------------------------------------------
// Helpers
// ---------------------------------------------------------------------------
__device__ __forceinline__ uint32_t smem_u32(const void* p) {
    uint32_t a;
    asm("{ .reg .u64 t; cvta.to.shared.u64 t, %1; cvt.u32.u64 %0, t; }" : "=r"(a) : "l"(p));
    return a;
}

#define CP_ASYNC_16(dst_u32, src_ptr) \
    asm volatile("cp.async.cg.shared.global [%0], [%1], 16;" \
                 :: "r"(dst_u32), "l"(src_ptr) : "memory")
#define CP_COMMIT() asm volatile("cp.async.commit_group;" ::: "memory")
#define CP_WAIT(n)  asm volatile("cp.async.wait_group %0;" :: "n"(n) : "memory")

#define LDSM_X4(r0, r1, r2, r3, addr) \
    asm volatile("ldmatrix.sync.aligned.m8n8.x4.shared.b16 {%0,%1,%2,%3}, [%4];" \
                 : "=r"(r0), "=r"(r1), "=r"(r2), "=r"(r3) : "r"(addr))

__device__ __forceinline__ float tf32r(float f) {
    uint32_t u;
    asm("cvt.rna.tf32.f32 %0, %1;" : "=r"(u) : "f"(f));
    return __uint_as_float(u);
}

__device__ __forceinline__ void mma_tf32(float* d, const uint32_t* a, const uint32_t* b) {
    asm volatile(
        "mma.sync.aligned.m16n8k8.row.col.f32.tf32.tf32.f32 "
        "{%0,%1,%2,%3}, {%4,%5,%6,%7}, {%8,%9}, {%0,%1,%2,%3};"
        : "+f"(d[0]), "+f"(d[1]), "+f"(d[2]), "+f"(d[3])
        : "r"(a[0]), "r"(a[1]), "r"(a[2]), "r"(a[3]),
          "r"(b[0]), "r"(b[1]));
}

// ---------------------------------------------------------------------------
// round_x: tf32-round, plain order (ldsm wants natural k layout)
// ---------------------------------------------------------------------------
__global__ void __launch_bounds__(256)
round_x_kernel(const float* __restrict__ x)
{
    size_t g = (size_t)blockIdx.x * 256 + threadIdx.x;   // 8-float group id
    float4 a = *(const float4*)(x + g * 8);
    float4 b = *(const float4*)(x + g * 8 + 4);
    a.x = tf32r(a.x); a.y = tf32r(a.y); a.z = tf32r(a.z); a.w = tf32r(a.w);
    b.x = tf32r(b.x); b.y = tf32r(b.y); b.z = tf32r(b.z); b.w = tf32r(b.w);
    *(float4*)(g_xr + g * 8)     = a;
    *(float4*)(g_xr + g * 8 + 4) = b;
}

// ---------------------------------------------------------------------------
// round_w: tf32-round + transpose W[k][n] -> n-major tiles (plain k order):
// g_wt tile (w, nb, kc) = [n 0..127][k 0..31], contiguous 16 KB.
// ---------------------------------------------------------------------------
__global__ void __launch_bounds__(256)
round_w_kernel(const float* __restrict__ Wq, const float* __restrict__ Wk,
               const float* __restrict__ Wv)
{
    __shared__ float s[32][136];
    const int kc = blockIdx.x, nb = blockIdx.y, w = blockIdx.z;
    const int tid = threadIdx.x;
    const float* W = (w == 0) ? Wq : (w == 1 ? Wk : Wv);

    #pragma unroll
    for (int i = 0; i < 4; i++) {
        int idx = tid + i * 256;
        int kr = idx >> 5, nc = idx & 31;
        float4 v = *(const float4*)(W + (size_t)(kc * 32 + kr) * N_W + nb * 128 + nc * 4);
        v.x = tf32r(v.x); v.y = tf32r(v.y); v.z = tf32r(v.z); v.w = tf32r(v.w);
        *(float4*)(&s[kr][nc * 4]) = v;
    }
    __syncthreads();

    float* out = g_wt + ((((size_t)w * 8 + nb) * 32 + kc) * 4096);
    #pragma unroll
    for (int i = 0; i < 4; i++) {
        int fidx = tid + i * 256;
        int n = fidx >> 3, pq = fidx & 7;
        float4 o;
        o.x = s[pq * 4 + 0][n];
        o.y = s[pq * 4 + 1][n];
        o.z = s[pq * 4 + 2][n];
        o.w = s[pq * 4 + 3][n];
        *(float4*)(out + n * 32 + pq * 4) = o;
    }
}

// ---------------------------------------------------------------------------
// Fused QKV GEMM: 128 threads, 4 warps (2m x 2n) of 64x64 each, occ 2.
// Fragments via ldmatrix.x4: per ks, 4 A-ldsm + 4 B-ldsm feed 32 MMAs.
// ---------------------------------------------------------------------------
__global__ void __launch_bounds__(128, 2)
qkv_gemm_kernel(const float* __restrict__ bq, const float* __restrict__ bk,
                const float* __restrict__ bv)
{
    extern __shared__ float smem[];
    float* As = smem;                       // [2][128][TROW]
    float* Bs = smem + 2 * TILE_F;          // [2][128][TROW] (n-major)
    const uint32_t sA = smem_u32(As);
    const uint32_t sB = smem_u32(Bs);

    const int tid = threadIdx.x;
    const int wid = tid >> 5;
    const int lane = tid & 31;
    const int r = lane >> 2;
    const int c = lane & 3;

    const int ntile = blockIdx.x;           // 0..23
    const int mtile = blockIdx.y;           // 0..127
    const int wsel  = ntile >> 3;
    const int nb    = ntile & 7;
    const int n0    = nb * BN;
    const int m0    = mtile * BM;
    const float* Wt   = g_wt + (((size_t)wsel * 8 + nb) * 32) * 4096;
    const float* bias = (wsel == 0) ? bq : (wsel == 1 ? bk : bv);

    const int wm = wid & 1;                 // 64-row group
    const int wn = wid >> 1;                // 64-col group

    // ldsm per-lane offsets (bytes)
    // A: lanes 0-15 -> rows 0-15 of the 16-row block, kq=0; lanes 16-31 same rows, kq=4
    const uint32_t laneA = (uint32_t)(((lane & 15) * TROW + (lane >> 4) * 4) * 4);
    // B: m0..m3 = (n0-7,k0-3),(n0-7,k4-7),(n8-15,k0-3),(n8-15,k4-7)
    const uint32_t laneB = (uint32_t)((((lane & 7) + ((lane >> 4) << 3)) * TROW
                                       + ((lane >> 3) & 1) * 4) * 4);

    auto load_tiles = [&](int kc, int buf) {
        const float* Ag = g_xr + (size_t)m0 * K_TOTAL + (size_t)kc * BK;
        const float* Bg = Wt + (size_t)kc * 4096;
        #pragma unroll
        for (int i = 0; i < 8; i++) {
            int idx = tid + i * 128;         // 0..1023
            int row = idx >> 3, q = idx & 7;
            uint32_t off = (uint32_t)(((buf * 128 + row) * TROW + q * 4) * 4);
            CP_ASYNC_16(sA + off, Ag + (size_t)row * K_TOTAL + q * 4);
            CP_ASYNC_16(sB + off, Bg + row * 32 + q * 4);
        }
        CP_COMMIT();
    };

    float acc[4][8][4];
    #pragma unroll
    for (int mt = 0; mt < 4; mt++)
        #pragma unroll
        for (int nt = 0; nt < 8; nt++)
            #pragma unroll
            for (int i = 0; i < 4; i++) acc[mt][nt][i] = 0.f;

    load_tiles(0, 0);

    for (int kc = 0; kc < NITER; kc++) {
        const int buf = kc & 1;
        if (kc + 1 < NITER) {
            load_tiles(kc + 1, buf ^ 1);
            CP_WAIT(1);
        } else {
            CP_WAIT(0);
        }
        __syncthreads();

        const uint32_t aBase = sA + (uint32_t)((buf * TILE_F + wm * 64 * TROW) * 4) + laneA;
        const uint32_t bBase = sB + (uint32_t)((buf * TILE_F + wn * 64 * TROW) * 4) + laneB;

        #pragma unroll
        for (int ks = 0; ks < 4; ks++) {
            const uint32_t kOff = (uint32_t)(ks * 8 * 4);
            uint32_t af[4][4];
            #pragma unroll
            for (int mt = 0; mt < 4; mt++)
                LDSM_X4(af[mt][0], af[mt][1], af[mt][2], af[mt][3],
                        aBase + (uint32_t)(mt * 16 * TROW * 4) + kOff);
            uint32_t bf[8][2];
            #pragma unroll
            for (int pr = 0; pr < 4; pr++)
                LDSM_X4(bf[2 * pr][0], bf[2 * pr][1], bf[2 * pr + 1][0], bf[2 * pr + 1][1],
                        bBase + (uint32_t)(pr * 16 * TROW * 4) + kOff);
            #pragma unroll
            for (int mt = 0; mt < 4; mt++)
                #pragma unroll
                for (int nt = 0; nt < 8; nt++)
                    mma_tf32(acc[mt][nt], af[mt], bf[nt]);
        }
        __syncthreads();
    }

    float* dst_w = g_qkv + (size_t)wsel * M_TOTAL * N_W;
    #pragma unroll
    for (int mt = 0; mt < 4; mt++) {
        const int row0 = m0 + wm * 64 + mt * 16 + r;
        #pragma unroll
        for (int nt = 0; nt < 8; nt++) {
            const int col = n0 + wn * 64 + nt * 8 + c * 2;
            const float b0 = __ldg(bias + col);
            const float b1 = __ldg(bias + col + 1);
            float2 v0 = make_float2(acc[mt][nt][0] + b0, acc[mt][nt][1] + b1);
            float2 v1 = make_float2(acc[mt][nt][2] + b0, acc[mt][nt][3] + b1);
            *(float2*)(dst_w + (size_t)row0 * N_W + col)       = v0;
            *(float2*)(dst_w + (size_t)(row0 + 8) * N_W + col) = v1;
        }
    }
}

// ---------------------------------------------------------------------------
// Head-attention: 4 tokens/block, 256 threads = 64 workers/token.
// SMEM 56.6 KB -> 4 blocks/SM = 50% occ (regs capped at 64).
// Scores: worker (ib,jb): rows ib*2..+2, cols jb*2..+2 (ib=sub>>3, jb=sub&7).
// Ctx: rows (sub>>4)*4..+4, cols (sub&15)*4..+4 -> acc 16 regs.
// ---------------------------------------------------------------------------
#define TPB_T 4
#define RS    68
#define TSTR  (16 * RS + 4)                  // 1092
#define PSTR  16
#define PTOK  (16 * PSTR + 4)                // 260
#define ATTN_SMEM_F (3 * TPB_T * TSTR + TPB_T * PTOK)   // 14144 floats
#define ATTN_SMEM_B (ATTN_SMEM_F * 4)                   // 56576 bytes

__global__ void __launch_bounds__(256, 4)
attn_kernel(float* __restrict__ out)
{
    extern __shared__ float sm[];
    float* sq  = sm;
    float* sk  = sm + TPB_T * TSTR;
    float* sv  = sm + 2 * TPB_T * TSTR;
    float* spT = sm + 3 * TPB_T * TSTR;

    const int tid = threadIdx.x;
    const int t0 = blockIdx.x * TPB_T;

    // Stage q,k,v: 1024 float4 per tensor, coalesced, 4 iters of 256 threads.
    {
        const float* qg = g_qkv + (size_t)t0 * N_W;
        const float* kg = g_qkv + (size_t)M_TOTAL * N_W + (size_t)t0 * N_W;
        const float* vg = g_qkv + 2ull * M_TOTAL * N_W + (size_t)t0 * N_W;
        #pragma unroll
        for (int i = 0; i < 4; i++) {
            int idx = tid + i * 256;            // 0..1023
            int tok = idx >> 8, rem = idx & 255;
            int row = rem >> 4, dq = rem & 15;
            int sa = tok * TSTR + row * RS + dq * 4;
            size_t ga = (size_t)idx * 4;
            *(float4*)(sq + sa) = *(const float4*)(qg + ga);
            *(float4*)(sk + sa) = *(const float4*)(kg + ga);
            *(float4*)(sv + sa) = *(const float4*)(vg + ga);
        }
    }
    __syncthreads();

    const int tt  = tid >> 6;    // token within block
    const int sub = tid & 63;
    const int ib  = sub >> 3;    // 0..7 -> 2 query rows
    const int jb  = sub & 7;     // 0..7 -> 2 key cols

    // ---- scores: 2x2 block ----
    float s[2][2];
    s[0][0] = s[0][1] = s[1][0] = s[1][1] = 0.f;
    {
        const float* qp = sq + tt * TSTR + (ib * 2) * RS;
        const float* kp = sk + tt * TSTR + (jb * 2) * RS;
        #pragma unroll
        for (int dq = 0; dq < 16; dq++) {
            float4 qa[2], ka[2];
            qa[0] = *(const float4*)(qp + dq * 4);
            qa[1] = *(const float4*)(qp + RS + dq * 4);
            ka[0] = *(const float4*)(kp + dq * 4);
            ka[1] = *(const float4*)(kp + RS + dq * 4);
            #pragma unroll
            for (int i = 0; i < 2; i++)
                #pragma unroll
                for (int j = 0; j < 2; j++) {
                    s[i][j] = fmaf(qa[i].x, ka[j].x, s[i][j]);
                    s[i][j] = fmaf(qa[i].y, ka[j].y, s[i][j]);
                    s[i][j] = fmaf(qa[i].z, ka[j].z, s[i][j]);
                    s[i][j] = fmaf(qa[i].w, ka[j].w, s[i][j]);
                }
        }
    }

    // ---- softmax over j: reduce across 8 jb-lanes (contiguous in warp) ----
    float p[2][2];
    #pragma unroll
    for (int i = 0; i < 2; i++) {
        float s0 = s[i][0] * 0.125f, s1 = s[i][1] * 0.125f;
        float m = fmaxf(s0, s1);
        m = fmaxf(m, __shfl_xor_sync(0xffffffffu, m, 1));
        m = fmaxf(m, __shfl_xor_sync(0xffffffffu, m, 2));
        m = fmaxf(m, __shfl_xor_sync(0xffffffffu, m, 4));
        float e0 = __expf(s0 - m), e1 = __expf(s1 - m);
        float sum = e0 + e1;
        sum += __shfl_xor_sync(0xffffffffu, sum, 1);
        sum += __shfl_xor_sync(0xffffffffu, sum, 2);
        sum += __shfl_xor_sync(0xffffffffu, sum, 4);
        float inv = __frcp_rn(sum);
        p[i][0] = e0 * inv; p[i][1] = e1 * inv;
    }
    // store transposed: spT[tok][j][i]
    {
        float* pt = spT + tt * PTOK;
        #pragma unroll
        for (int j = 0; j < 2; j++)
            *(float2*)(pt + (jb * 2 + j) * PSTR + ib * 2) = make_float2(p[0][j], p[1][j]);
    }
    __syncthreads();   // probs per token span 2 warps

    // ---- ctx: rows i0..i0+4, cols c0..c0+4 ----
    {
        const int i0 = (sub >> 4) * 4;       // 0,4,8,12
        const int c0 = (sub & 15) * 4;       // 0..60
        const float* pt = spT + tt * PTOK;
        const float* vp = sv + tt * TSTR + c0;
        float4 acc[4];
        #pragma unroll
        for (int i = 0; i < 4; i++) acc[i] = make_float4(0.f, 0.f, 0.f, 0.f);
        #pragma unroll
        for (int j = 0; j < 16; j++) {
            float4 vj = *(const float4*)(vp + j * RS);
            float4 pj = *(const float4*)(pt + j * PSTR + i0);
            const float pa[4] = {pj.x, pj.y, pj.z, pj.w};
            #pragma unroll
            for (int i = 0; i < 4; i++) {
                acc[i].x = fmaf(pa[i], vj.x, acc[i].x);
                acc[i].y = fmaf(pa[i], vj.y, acc[i].y);
                acc[i].z = fmaf(pa[i], vj.z, acc[i].z);
                acc[i].w = fmaf(pa[i], vj.w, acc[i].w);
            }
        }
        float* ob = out + (size_t)(t0 + tt) * N_W + (size_t)i0 * 64 + c0;
        #pragma unroll
        for (int i = 0; i < 4; i++)
            *(float4*)(ob + i * 64) = acc[i];
    }
}

// ---------------------------------------------------------------------------
// Launch
// ---------------------------------------------------------------------------
extern "C" void kernel_launch(void* const* d_in, const int* in_sizes, int n_in,
                              void* d_out, int out_size)
{
    const float* x  = (const float*)d_in[0];
    const float* Wq = (const float*)d_in[1];
    const float* bq = (const float*)d_in[2];
    const float* Wk = (const float*)d_in[3];
    const float* bk = (const float*)d_in[4];
    const float* Wv = (const float*)d_in[5];
    const float* bv = (const float*)d_in[6];
    float* out = (float*)d_out;

    cudaFuncSetAttribute(qkv_gemm_kernel,
                         cudaFuncAttributeMaxDynamicSharedMemorySize, SMEM_BYTES);
    cudaFuncSetAttribute(attn_kernel,
                         cudaFuncAttributeMaxDynamicSharedMemorySize, ATTN_SMEM_B);

    round_x_kernel<<<(M_TOTAL * K_TOTAL / 8) / 256, 256>>>(x);
    {
        dim3 gw(32, 8, 3);
        round_w_kernel<<<gw, 256>>>(Wq, Wk, Wv);
    }
    dim3 grid(24, 128);
    qkv_gemm_kernel<<<grid, 128, SMEM_BYTES>>>(bq, bk, bv);
    attn_kernel<<<M_TOTAL / TPB_T, 256, ATTN_SMEM_B>>>(out);
}

// round 7
// speedup vs baseline: 1.0842x; 1.0257x over previous
#include <cuda_runtime.h>
#include <cstdint>

// ---------------------------------------------------------------------------
// Problem constants
// ---------------------------------------------------------------------------
#define M_TOTAL 16384
#define N_W     1024
#define K_TOTAL 1024

// GEMM tiling: CTA 128x128, 8 warps of 64x32, BK=32 (one K32 int8 MMA per kc)
#define BM 128
#define BN 128
#define BK 32
#define NITER (K_TOTAL / BK)   // 32

#define RSTRIDE 80                       // bytes per smem row (64 data + 16 pad)
#define STAGE_T (128 * RSTRIDE)          // 10240 B per tile
#define SMEM_BYTES (4 * STAGE_T)         // 2 stages x (A+B) = 40960 B

// Scales: xq = round(x * 2^11), wq = round(w * 2^17); combined 2^28.
#define SX 2048.0f
#define SW 131072.0f
#define INV_SCALE 3.725290298461914e-9f  // 2^-28
#define QCLAMP 16128

// Scratch
__device__ float   g_qkv[3ull * M_TOTAL * N_W];          // QKV projections (fp32)
__device__ int8_t  g_xq[(size_t)M_TOTAL * 2048];         // x rows: per-kc [hi32|lo32]
__device__ int8_t  g_wq[3ull * 8 * 32 * 8192];           // W tiles: [n128][lo32|hi32]

// ---------------------------------------------------------------------------
// Helpers
// ---------------------------------------------------------------------------
__device__ __forceinline__ uint32_t smem_u32(const void* p) {
    uint32_t a;
    asm("{ .reg .u64 t; cvta.to.shared.u64 t, %1; cvt.u32.u64 %0, t; }" : "=r"(a) : "l"(p));
    return a;
}

#define CP_ASYNC_16(dst_u32, src_ptr) \
    asm volatile("cp.async.cg.shared.global [%0], [%1], 16;" \
                 :: "r"(dst_u32), "l"(src_ptr) : "memory")
#define CP_COMMIT() asm volatile("cp.async.commit_group;" ::: "memory")
#define CP_WAIT(n)  asm volatile("cp.async.wait_group %0;" :: "n"(n) : "memory")

#define LDSM_X4(r0, r1, r2, r3, addr) \
    asm volatile("ldmatrix.sync.aligned.m8n8.x4.shared.b16 {%0,%1,%2,%3}, [%4];" \
                 : "=r"(r0), "=r"(r1), "=r"(r2), "=r"(r3) : "r"(addr))

__device__ __forceinline__ void mma_s8(int* d, const uint32_t* a, const uint32_t* b) {
    asm volatile(
        "mma.sync.aligned.m16n8k32.row.col.s32.s8.s8.s32 "
        "{%0,%1,%2,%3}, {%4,%5,%6,%7}, {%8,%9}, {%0,%1,%2,%3};"
        : "+r"(d[0]), "+r"(d[1]), "+r"(d[2]), "+r"(d[3])
        : "r"(a[0]), "r"(a[1]), "r"(a[2]), "r"(a[3]),
          "r"(b[0]), "r"(b[1]));
}

__device__ __forceinline__ uint32_t pack4(int a, int b, int c, int d) {
    return (uint32_t)(a & 0xFF) | ((uint32_t)(b & 0xFF) << 8) |
           ((uint32_t)(c & 0xFF) << 16) | ((uint32_t)(d & 0xFF) << 24);
}

// quantize to int16 range and split: q = 128*hi + lo, hi in [-126,126], lo in [-64,63]
__device__ __forceinline__ void qsplit(float v, float scale, int& hi, int& lo) {
    int q = __float2int_rn(v * scale);
    q = max(-QCLAMP, min(QCLAMP, q));
    hi = ((q + 16448) >> 7) - 128;       // round-to-nearest
    lo = q - (hi << 7);
}

// ---------------------------------------------------------------------------
// quant_x: x fp32 -> per-row, per-kc chunks of [hi 32B | lo 32B]
// One thread per 32-k chunk. Reads/writes coalesced.
// ---------------------------------------------------------------------------
__global__ void __launch_bounds__(256)
quant_x_kernel(const float* __restrict__ x)
{
    const size_t t = (size_t)blockIdx.x * 256 + threadIdx.x;  // 0 .. 16384*32-1
    const size_t row = t >> 5;
    const int chunk = (int)(t & 31);
    const float* src = x + row * K_TOTAL + chunk * 32;

    int hi[32], lo[32];
    #pragma unroll
    for (int i = 0; i < 8; i++) {
        float4 v = *(const float4*)(src + i * 4);
        qsplit(v.x, SX, hi[i * 4 + 0], lo[i * 4 + 0]);
        qsplit(v.y, SX, hi[i * 4 + 1], lo[i * 4 + 1]);
        qsplit(v.z, SX, hi[i * 4 + 2], lo[i * 4 + 2]);
        qsplit(v.w, SX, hi[i * 4 + 3], lo[i * 4 + 3]);
    }
    uint4 h0, h1, l0, l1;
    h0.x = pack4(hi[0], hi[1], hi[2], hi[3]);    h0.y = pack4(hi[4], hi[5], hi[6], hi[7]);
    h0.z = pack4(hi[8], hi[9], hi[10], hi[11]);  h0.w = pack4(hi[12], hi[13], hi[14], hi[15]);
    h1.x = pack4(hi[16], hi[17], hi[18], hi[19]); h1.y = pack4(hi[20], hi[21], hi[22], hi[23]);
    h1.z = pack4(hi[24], hi[25], hi[26], hi[27]); h1.w = pack4(hi[28], hi[29], hi[30], hi[31]);
    l0.x = pack4(lo[0], lo[1], lo[2], lo[3]);    l0.y = pack4(lo[4], lo[5], lo[6], lo[7]);
    l0.z = pack4(lo[8], lo[9], lo[10], lo[11]);  l0.w = pack4(lo[12], lo[13], lo[14], lo[15]);
    l1.x = pack4(lo[16], lo[17], lo[18], lo[19]); l1.y = pack4(lo[20], lo[21], lo[22], lo[23]);
    l1.z = pack4(lo[24], lo[25], lo[26], lo[27]); l1.w = pack4(lo[28], lo[29], lo[30], lo[31]);

    int8_t* dst = g_xq + row * 2048 + chunk * 64;
    *(uint4*)(dst)      = h0;
    *(uint4*)(dst + 16) = h1;
    *(uint4*)(dst + 32) = l0;
    *(uint4*)(dst + 48) = l1;
}

// ---------------------------------------------------------------------------
// quant_w: W[k][n] -> n-major tiles (w, nb, kc): [n 0..127][lo 32B | hi 32B]
// Grid (32 kc, 8 nb, 3 w), 256 threads: thread = (n = tid&127, kh = tid>>7).
// Reads coalesced across n; writes 16B at stride 64 (small volume).
// ---------------------------------------------------------------------------
__global__ void __launch_bounds__(256)
quant_w_kernel(const float* __restrict__ Wq, const float* __restrict__ Wk,
               const float* __restrict__ Wv)
{
    const int kc = blockIdx.x, nb = blockIdx.y, w = blockIdx.z;
    const int n  = threadIdx.x & 127;
    const int kh = threadIdx.x >> 7;     // 0/1 -> k 0..15 / 16..31 within chunk
    const float* W = (w == 0) ? Wq : (w == 1 ? Wk : Wv);

    int hi[16], lo[16];
    #pragma unroll
    for (int j = 0; j < 16; j++) {
        float v = W[(size_t)(kc * 32 + kh * 16 + j) * N_W + nb * 128 + n];
        qsplit(v, SW, hi[j], lo[j]);
    }
    uint4 hq, lq;
    lq.x = pack4(lo[0], lo[1], lo[2], lo[3]);    lq.y = pack4(lo[4], lo[5], lo[6], lo[7]);
    lq.z = pack4(lo[8], lo[9], lo[10], lo[11]);  lq.w = pack4(lo[12], lo[13], lo[14], lo[15]);
    hq.x = pack4(hi[0], hi[1], hi[2], hi[3]);    hq.y = pack4(hi[4], hi[5], hi[6], hi[7]);
    hq.z = pack4(hi[8], hi[9], hi[10], hi[11]);  hq.w = pack4(hi[12], hi[13], hi[14], hi[15]);

    int8_t* dst = g_wq + (((size_t)w * 8 + nb) * 32 + kc) * 8192 + (size_t)n * 64;
    *(uint4*)(dst + kh * 16)      = lq;   // lo at bytes [0,32)
    *(uint4*)(dst + 32 + kh * 16) = hq;   // hi at bytes [32,64)
}

// ---------------------------------------------------------------------------
// Fused QKV GEMM (int8 split): 256 threads, 8 warps (2m x 4n) of 64x32.
// Per kc: 12 ldsm.x4 + 48 s8 MMAs per warp. Two int32 accumulator sets.
// out = (16384*acc_hh + 128*acc_cross) * 2^-28 + bias
// ---------------------------------------------------------------------------
__global__ void __launch_bounds__(256, 1)
qkv_gemm_kernel(const float* __restrict__ bq, const float* __restrict__ bk,
                const float* __restrict__ bv)
{
    extern __shared__ char smem[];
    const uint32_t sA = smem_u32(smem);            // [2][128][RSTRIDE]  (A: hi|lo)
    const uint32_t sB = sA + 2 * STAGE_T;          // [2][128][RSTRIDE]  (B: lo|hi)

    const int tid = threadIdx.x;
    const int wid = tid >> 5;
    const int lane = tid & 31;
    const int r = lane >> 2;
    const int c = lane & 3;

    const int ntile = blockIdx.x;           // 0..23
    const int mtile = blockIdx.y;           // 0..127
    const int wsel  = ntile >> 3;
    const int nb    = ntile & 7;
    const int n0    = nb * BN;
    const int m0    = mtile * BM;
    const int8_t* Wt = g_wq + (((size_t)wsel * 8 + nb) * 32) * 8192;
    const float* bias = (wsel == 0) ? bq : (wsel == 1 ? bk : bv);

    const int wm = wid & 1;                 // 64-row group
    const int wn = wid >> 1;                // 32-col group (0..3)

    // ldsm per-lane address offsets (bytes)
    const uint32_t laneA = (uint32_t)((lane & 15) * RSTRIDE + (lane >> 4) * 16);
    const uint32_t laneB = (uint32_t)(((lane & 7) + ((lane >> 4) << 3)) * RSTRIDE
                                      + ((lane >> 3) & 1) * 16);

    auto load_tiles = [&](int kc, int buf) {
        const int8_t* Ag = g_xq + (size_t)m0 * 2048 + (size_t)kc * 64;
        const int8_t* Bg = Wt + (size_t)kc * 8192;
        #pragma unroll
        for (int i = 0; i < 2; i++) {
            int idx = tid + i * 256;         // 0..511: A chunks
            int row = idx >> 2, q = idx & 3;
            CP_ASYNC_16(sA + (uint32_t)(buf * STAGE_T + row * RSTRIDE + q * 16),
                        Ag + (size_t)row * 2048 + q * 16);
        }
        #pragma unroll
        for (int i = 0; i < 2; i++) {
            int idx = tid + i * 256;         // 0..511: B chunks
            int row = idx >> 2, q = idx & 3;
            CP_ASYNC_16(sB + (uint32_t)(buf * STAGE_T + row * RSTRIDE + q * 16),
                        Bg + (size_t)row * 64 + q * 16);
        }
        CP_COMMIT();
    };

    int acc_hh[4][4][4], acc_cr[4][4][4];
    #pragma unroll
    for (int mt = 0; mt < 4; mt++)
        #pragma unroll
        for (int nt = 0; nt < 4; nt++)
            #pragma unroll
            for (int i = 0; i < 4; i++) { acc_hh[mt][nt][i] = 0; acc_cr[mt][nt][i] = 0; }

    load_tiles(0, 0);

    for (int kc = 0; kc < NITER; kc++) {
        const int buf = kc & 1;
        if (kc + 1 < NITER) {
            load_tiles(kc + 1, buf ^ 1);
            CP_WAIT(1);
        } else {
            CP_WAIT(0);
        }
        __syncthreads();

        const uint32_t aBase = sA + (uint32_t)(buf * STAGE_T + wm * 64 * RSTRIDE) + laneA;
        const uint32_t bBase = sB + (uint32_t)(buf * STAGE_T + wn * 32 * RSTRIDE) + laneB;

        uint32_t aHi[4][4], aLo[4][4];
        #pragma unroll
        for (int mt = 0; mt < 4; mt++) {
            LDSM_X4(aHi[mt][0], aHi[mt][1], aHi[mt][2], aHi[mt][3],
                    aBase + (uint32_t)(mt * 16 * RSTRIDE));
            LDSM_X4(aLo[mt][0], aLo[mt][1], aLo[mt][2], aLo[mt][3],
                    aBase + (uint32_t)(mt * 16 * RSTRIDE) + 32);
        }
        uint32_t bLo[4][2], bHi[4][2];
        #pragma unroll
        for (int pr = 0; pr < 2; pr++) {
            LDSM_X4(bLo[2 * pr][0], bLo[2 * pr][1], bLo[2 * pr + 1][0], bLo[2 * pr + 1][1],
                    bBase + (uint32_t)(pr * 16 * RSTRIDE));
            LDSM_X4(bHi[2 * pr][0], bHi[2 * pr][1], bHi[2 * pr + 1][0], bHi[2 * pr + 1][1],
                    bBase + (uint32_t)(pr * 16 * RSTRIDE) + 32);
        }

        #pragma unroll
        for (int mt = 0; mt < 4; mt++)
            #pragma unroll
            for (int nt = 0; nt < 4; nt++) {
                mma_s8(acc_hh[mt][nt], aHi[mt], bHi[nt]);
                mma_s8(acc_cr[mt][nt], aHi[mt], bLo[nt]);
                mma_s8(acc_cr[mt][nt], aLo[mt], bHi[nt]);
            }
        __syncthreads();
    }

    float* dst_w = g_qkv + (size_t)wsel * M_TOTAL * N_W;
    #pragma unroll
    for (int mt = 0; mt < 4; mt++) {
        const int row0 = m0 + wm * 64 + mt * 16 + r;
        #pragma unroll
        for (int nt = 0; nt < 4; nt++) {
            const int col = n0 + wn * 32 + nt * 8 + c * 2;
            const float b0 = __ldg(bias + col);
            const float b1 = __ldg(bias + col + 1);
            float2 v0, v1;
            v0.x = ((float)acc_hh[mt][nt][0] * 16384.f + (float)acc_cr[mt][nt][0] * 128.f) * INV_SCALE + b0;
            v0.y = ((float)acc_hh[mt][nt][1] * 16384.f + (float)acc_cr[mt][nt][1] * 128.f) * INV_SCALE + b1;
            v1.x = ((float)acc_hh[mt][nt][2] * 16384.f + (float)acc_cr[mt][nt][2] * 128.f) * INV_SCALE + b0;
            v1.y = ((float)acc_hh[mt][nt][3] * 16384.f + (float)acc_cr[mt][nt][3] * 128.f) * INV_SCALE + b1;
            *(float2*)(dst_w + (size_t)row0 * N_W + col)       = v0;
            *(float2*)(dst_w + (size_t)(row0 + 8) * N_W + col) = v1;
        }
    }
}

// ---------------------------------------------------------------------------
// Head-attention (R5 config — best measured: 75.1 us).
// 4 tokens/block, 128 threads, 32 workers/token.
// ---------------------------------------------------------------------------
#define TPB_T 4
#define RS    68
#define TSTR  (16 * RS + 4)                  // 1092
#define PSTR  16
#define PTOK  (16 * PSTR + 4)                // 260
#define ATTN_SMEM_F (3 * TPB_T * TSTR + TPB_T * PTOK)   // 14144 floats
#define ATTN_SMEM_B (ATTN_SMEM_F * 4)                   // 56576 bytes

__global__ void __launch_bounds__(128, 4)
attn_kernel(float* __restrict__ out)
{
    extern __shared__ float sm[];
    float* sq  = sm;
    float* sk  = sm + TPB_T * TSTR;
    float* sv  = sm + 2 * TPB_T * TSTR;
    float* spT = sm + 3 * TPB_T * TSTR;

    const int tid = threadIdx.x;
    const int t0 = blockIdx.x * TPB_T;

    {
        const float* qg = g_qkv + (size_t)t0 * N_W;
        const float* kg = g_qkv + (size_t)M_TOTAL * N_W + (size_t)t0 * N_W;
        const float* vg = g_qkv + 2ull * M_TOTAL * N_W + (size_t)t0 * N_W;
        #pragma unroll
        for (int i = 0; i < 8; i++) {
            int idx = tid + i * 128;            // 0..1023
            int tok = idx >> 8, rem = idx & 255;
            int row = rem >> 4, dq = rem & 15;
            int sa = tok * TSTR + row * RS + dq * 4;
            size_t ga = (size_t)idx * 4;
            *(float4*)(sq + sa) = *(const float4*)(qg + ga);
            *(float4*)(sk + sa) = *(const float4*)(kg + ga);
            *(float4*)(sv + sa) = *(const float4*)(vg + ga);
        }
    }
    __syncthreads();

    const int tt  = tid >> 5;
    const int sub = tid & 31;
    const int ib  = sub >> 3;
    const int jb  = sub & 7;

    float s[4][2];
    #pragma unroll
    for (int i = 0; i < 4; i++) { s[i][0] = 0.f; s[i][1] = 0.f; }
    {
        const float* qp = sq + tt * TSTR + (ib * 4) * RS;
        const float* kp = sk + tt * TSTR + (jb * 2) * RS;
        #pragma unroll
        for (int dq = 0; dq < 16; dq++) {
            float4 qa[4], ka[2];
            #pragma unroll
            for (int i = 0; i < 4; i++) qa[i] = *(const float4*)(qp + i * RS + dq * 4);
            #pragma unroll
            for (int j = 0; j < 2; j++) ka[j] = *(const float4*)(kp + j * RS + dq * 4);
            #pragma unroll
            for (int i = 0; i < 4; i++)
                #pragma unroll
                for (int j = 0; j < 2; j++) {
                    s[i][j] = fmaf(qa[i].x, ka[j].x, s[i][j]);
                    s[i][j] = fmaf(qa[i].y, ka[j].y, s[i][j]);
                    s[i][j] = fmaf(qa[i].z, ka[j].z, s[i][j]);
                    s[i][j] = fmaf(qa[i].w, ka[j].w, s[i][j]);
                }
        }
    }

    float p[4][2];
    #pragma unroll
    for (int i = 0; i < 4; i++) {
        float s0 = s[i][0] * 0.125f, s1 = s[i][1] * 0.125f;
        float m = fmaxf(s0, s1);
        m = fmaxf(m, __shfl_xor_sync(0xffffffffu, m, 1));
        m = fmaxf(m, __shfl_xor_sync(0xffffffffu, m, 2));
        m = fmaxf(m, __shfl_xor_sync(0xffffffffu, m, 4));
        float e0 = __expf(s0 - m), e1 = __expf(s1 - m);
        float sum = e0 + e1;
        sum += __shfl_xor_sync(0xffffffffu, sum, 1);
        sum += __shfl_xor_sync(0xffffffffu, sum, 2);
        sum += __shfl_xor_sync(0xffffffffu, sum, 4);
        float inv = __frcp_rn(sum);
        p[i][0] = e0 * inv; p[i][1] = e1 * inv;
    }
    {
        float* pt = spT + tt * PTOK;
        #pragma unroll
        for (int j = 0; j < 2; j++) {
            float4 v = make_float4(p[0][j], p[1][j], p[2][j], p[3][j]);
            *(float4*)(pt + (jb * 2 + j) * PSTR + ib * 4) = v;
        }
    }
    __syncwarp();

    {
        const int i0 = (sub >> 4) * 8;
        const int c0 = (sub & 15) * 4;
        const float* pt = spT + tt * PTOK;
        const float* vp = sv + tt * TSTR + c0;
        float4 acc[8];
        #pragma unroll
        for (int i = 0; i < 8; i++) acc[i] = make_float4(0.f, 0.f, 0.f, 0.f);
        #pragma unroll
        for (int j = 0; j < 16; j++) {
            float4 vj = *(const float4*)(vp + j * RS);
            const float* pr = pt + j * PSTR + i0;
            float4 p0 = *(const float4*)(pr);
            float4 p1 = *(const float4*)(pr + 4);
            const float pj[8] = {p0.x, p0.y, p0.z, p0.w, p1.x, p1.y, p1.z, p1.w};
            #pragma unroll
            for (int i = 0; i < 8; i++) {
                acc[i].x = fmaf(pj[i], vj.x, acc[i].x);
                acc[i].y = fmaf(pj[i], vj.y, acc[i].y);
                acc[i].z = fmaf(pj[i], vj.z, acc[i].z);
                acc[i].w = fmaf(pj[i], vj.w, acc[i].w);
            }
        }
        float* ob = out + (size_t)(t0 + tt) * N_W + (size_t)i0 * 64 + c0;
        #pragma unroll
        for (int i = 0; i < 8; i++)
            *(float4*)(ob + i * 64) = acc[i];
    }
}

// ---------------------------------------------------------------------------
// Launch
// ---------------------------------------------------------------------------
extern "C" void kernel_launch(void* const* d_in, const int* in_sizes, int n_in,
                              void* d_out, int out_size)
{
    const float* x  = (const float*)d_in[0];
    const float* Wq = (const float*)d_in[1];
    const float* bq = (const float*)d_in[2];
    const float* Wk = (const float*)d_in[3];
    const float* bk = (const float*)d_in[4];
    const float* Wv = (const float*)d_in[5];
    const float* bv = (const float*)d_in[6];
    float* out = (float*)d_out;

    cudaFuncSetAttribute(qkv_gemm_kernel,
                         cudaFuncAttributeMaxDynamicSharedMemorySize, SMEM_BYTES);
    cudaFuncSetAttribute(attn_kernel,
                         cudaFuncAttributeMaxDynamicSharedMemorySize, ATTN_SMEM_B);

    quant_x_kernel<<<(M_TOTAL * 32) / 256, 256>>>(x);
    {
        dim3 gw(32, 8, 3);
        quant_w_kernel<<<gw, 256>>>(Wq, Wk, Wv);
    }
    dim3 grid(24, 128);
    qkv_gemm_kernel<<<grid, 256, SMEM_BYTES>>>(bq, bk, bv);
    attn_kernel<<<M_TOTAL / TPB_T, 128, ATTN_SMEM_B>>>(out);
}